// round 1
// baseline (speedup 1.0000x reference)
#include <cuda_runtime.h>
#include <math.h>
#include <stdint.h>

// INGP hashgrid encoding:
//   out[n, l*2 + f] = sum_{c in 8 corners} w_c(n,l) * tables[l, hash(cell_c) & (T-1), f]
// N = 524288 points, L = 16 levels, T = 2^19, F = 2.

#define NPTS   524288
#define NLEV   16
#define TSIZE  (1u << 19)
#define HMASK  (TSIZE - 1u)
#define PRIME1 2654435761u
#define PRIME2 805459861u

struct ResArr { float r[NLEV]; };

__global__ __launch_bounds__(256) void ingp_encode_kernel(
    const float*  __restrict__ pts,     // [N,3]
    const float2* __restrict__ tables,  // [L, T] of float2 (F=2)
    float2*       __restrict__ out,     // [N, 16] of float2  (== [N,32] floats)
    ResArr res)
{
    int t = blockIdx.x * blockDim.x + threadIdx.x;
    int n = t >> 4;          // point index
    int l = t & 15;          // level index
    if (n >= NPTS) return;

    // Load the point (16 threads share it -> L1 broadcast)
    float px = pts[3 * n + 0];
    float py = pts[3 * n + 1];
    float pz = pts[3 * n + 2];

    // x = (p - VMIN) / (VMAX - VMIN) = (p + 1) / 2   — exact ops, no contraction
    float xs = __fmul_rn(__fadd_rn(px, 1.0f), 0.5f);
    float ys = __fmul_rn(__fadd_rn(py, 1.0f), 0.5f);
    float zs = __fmul_rn(__fadd_rn(pz, 1.0f), 0.5f);

    float r = res.r[l];
    float posx = __fmul_rn(xs, r);
    float posy = __fmul_rn(ys, r);
    float posz = __fmul_rn(zs, r);

    float fx = floorf(posx), fy = floorf(posy), fz = floorf(posz);
    float wx = __fsub_rn(posx, fx);
    float wy = __fsub_rn(posy, fy);
    float wz = __fsub_rn(posz, fz);

    uint32_t ix = (uint32_t)fx;
    uint32_t iy = (uint32_t)fy;
    uint32_t iz = (uint32_t)fz;

    // NGP spatial hash: h = c0*1 ^ c1*PRIME1 ^ c2*PRIME2  (uint32 wraparound)
    uint32_t hx0 = ix;
    uint32_t hx1 = ix + 1u;
    uint32_t hy0 = iy * PRIME1;
    uint32_t hy1 = hy0 + PRIME1;
    uint32_t hz0 = iz * PRIME2;
    uint32_t hz1 = hz0 + PRIME2;

    const float2* __restrict__ tab = tables + (size_t)l * TSIZE;

    // Issue all 8 independent gathers up front (MLP = 8)
    float2 v000 = __ldg(tab + ((hx0 ^ hy0 ^ hz0) & HMASK));
    float2 v001 = __ldg(tab + ((hx0 ^ hy0 ^ hz1) & HMASK));
    float2 v010 = __ldg(tab + ((hx0 ^ hy1 ^ hz0) & HMASK));
    float2 v011 = __ldg(tab + ((hx0 ^ hy1 ^ hz1) & HMASK));
    float2 v100 = __ldg(tab + ((hx1 ^ hy0 ^ hz0) & HMASK));
    float2 v101 = __ldg(tab + ((hx1 ^ hy0 ^ hz1) & HMASK));
    float2 v110 = __ldg(tab + ((hx1 ^ hy1 ^ hz0) & HMASK));
    float2 v111 = __ldg(tab + ((hx1 ^ hy1 ^ hz1) & HMASK));

    // Trilinear corner weights (corner bit set -> w, else 1-w), per CORNERS order
    float ux0 = 1.0f - wx, ux1 = wx;
    float uy0 = 1.0f - wy, uy1 = wy;
    float uz0 = 1.0f - wz, uz1 = wz;

    float w000 = ux0 * uy0 * uz0;
    float w001 = ux0 * uy0 * uz1;
    float w010 = ux0 * uy1 * uz0;
    float w011 = ux0 * uy1 * uz1;
    float w100 = ux1 * uy0 * uz0;
    float w101 = ux1 * uy0 * uz1;
    float w110 = ux1 * uy1 * uz0;
    float w111 = ux1 * uy1 * uz1;

    float2 acc;
    acc.x = w000 * v000.x + w001 * v001.x + w010 * v010.x + w011 * v011.x
          + w100 * v100.x + w101 * v101.x + w110 * v110.x + w111 * v111.x;
    acc.y = w000 * v000.y + w001 * v001.y + w010 * v010.y + w011 * v011.y
          + w100 * v100.y + w101 * v101.y + w110 * v110.y + w111 * v111.y;

    // out[n, l] as float2 -> contiguous 256B per warp
    out[(size_t)n * NLEV + l] = acc;
}

extern "C" void kernel_launch(void* const* d_in, const int* in_sizes, int n_in,
                              void* d_out, int out_size)
{
    const float*  pts    = (const float*)d_in[0];   // [N,3] float32
    const float2* tables = (const float2*)d_in[1];  // [L,T,2] float32 -> [L,T] float2

    // Replicate numpy exactly:
    //   GROWTH = np.exp((np.log(2048) - np.log(16)) / 15)   (float64, libm)
    //   RES    = np.floor(16 * GROWTH ** arange(16)).astype(float32)
    ResArr res;
    {
        double growth = exp((log(2048.0) - log(16.0)) / 15.0);
        for (int l = 0; l < NLEV; l++)
            res.r[l] = (float)floor(16.0 * pow(growth, (double)l));
    }

    int total  = NPTS * NLEV;
    int block  = 256;
    int grid   = (total + block - 1) / block;
    ingp_encode_kernel<<<grid, block>>>(pts, tables, (float2*)d_out, res);
}

// round 2
// speedup vs baseline: 1.1081x; 1.1081x over previous
#include <cuda_runtime.h>
#include <math.h>
#include <stdint.h>

// INGP hashgrid encoding:
//   out[n, l*2 + f] = sum_{c in 8 corners} w_c(n,l) * tables[l, hash(cell_c) & (T-1), f]
// N = 524288 points, L = 16 levels, T = 2^19, F = 2.
//
// Key trick: hash = ix*1 ^ iy*P1 ^ iz*P2. When ix is even, the x+1 corner's
// index is idx^1, so both x-corners live in one aligned float4 -> one LDG.128
// instead of two LDG.64 (halves l1tex wavefronts for that pair).
// Fine levels (l>=3) bypass L1 (.cg) so coarse tables stay L1-resident.

#define NPTS   524288
#define NLEV   16
#define TSIZE  (1u << 19)
#define HMASK  (TSIZE - 1u)
#define PRIME1 2654435761u
#define PRIME2 805459861u

struct ResArr { float r[NLEV]; };

__global__ __launch_bounds__(256) void ingp_encode_kernel(
    const float*  __restrict__ pts,     // [N,3]
    const float2* __restrict__ tables,  // [L, T] of float2 (F=2)
    float2*       __restrict__ out,     // [N, 16] of float2
    ResArr res)
{
    int t = blockIdx.x * blockDim.x + threadIdx.x;   // grid is exact: N*L/256
    int n = t >> 4;          // point index
    int l = t & 15;          // level index

    // 16 consecutive threads share a point -> L1 broadcast
    float px = pts[3 * n + 0];
    float py = pts[3 * n + 1];
    float pz = pts[3 * n + 2];

    // x = (p + 1) / 2 — exact ops, no FMA contraction
    float xs = __fmul_rn(__fadd_rn(px, 1.0f), 0.5f);
    float ys = __fmul_rn(__fadd_rn(py, 1.0f), 0.5f);
    float zs = __fmul_rn(__fadd_rn(pz, 1.0f), 0.5f);

    float r = res.r[l];
    float posx = __fmul_rn(xs, r);
    float posy = __fmul_rn(ys, r);
    float posz = __fmul_rn(zs, r);

    float fx = floorf(posx), fy = floorf(posy), fz = floorf(posz);
    float wx = __fsub_rn(posx, fx);
    float wy = __fsub_rn(posy, fy);
    float wz = __fsub_rn(posz, fz);

    uint32_t ix = (uint32_t)fx;
    uint32_t iy = (uint32_t)fy;
    uint32_t iz = (uint32_t)fz;

    uint32_t hy0 = iy * PRIME1;
    uint32_t hy1 = hy0 + PRIME1;
    uint32_t hz0 = iz * PRIME2;
    uint32_t hz1 = hz0 + PRIME2;

    // 4 (y,z) pair bases for the x=0 corner, in CORNERS order (y0z0,y0z1,y1z0,y1z1)
    uint32_t rest[4];
    rest[0] = hy0 ^ hz0;
    rest[1] = hy0 ^ hz1;
    rest[2] = hy1 ^ hz0;
    rest[3] = hy1 ^ hz1;

    const float2* __restrict__ tab  = tables + (size_t)l * TSIZE;
    const float4* __restrict__ tab4 = (const float4*)tab;

    bool cg = (l >= 3);   // fine levels: bypass L1

    float2 v0[4];   // x=0 corner values per (y,z) pair
    float2 v1[4];   // x=1 corner values per (y,z) pair

    if ((ix & 1u) == 0u) {
        // Even ix: x+1 corner index == base^1 -> one aligned float4 per pair
        uint32_t b[4];
        float4 q[4];
        #pragma unroll
        for (int i = 0; i < 4; i++) {
            b[i] = (ix ^ rest[i]) & HMASK;
            q[i] = cg ? __ldcg(tab4 + (b[i] >> 1)) : __ldg(tab4 + (b[i] >> 1));
        }
        #pragma unroll
        for (int i = 0; i < 4; i++) {
            bool lo = (b[i] & 1u) == 0u;   // base in low half of the float4?
            v0[i] = lo ? make_float2(q[i].x, q[i].y) : make_float2(q[i].z, q[i].w);
            v1[i] = lo ? make_float2(q[i].z, q[i].w) : make_float2(q[i].x, q[i].y);
        }
    } else {
        // Odd ix: corners land in unrelated buckets -> 8 independent float2 loads
        uint32_t ix1 = ix + 1u;
        uint32_t b0[4], b1[4];
        #pragma unroll
        for (int i = 0; i < 4; i++) {
            b0[i] = (ix  ^ rest[i]) & HMASK;
            b1[i] = (ix1 ^ rest[i]) & HMASK;
        }
        #pragma unroll
        for (int i = 0; i < 4; i++) {
            v0[i] = cg ? __ldcg(tab + b0[i]) : __ldg(tab + b0[i]);
            v1[i] = cg ? __ldcg(tab + b1[i]) : __ldg(tab + b1[i]);
        }
    }

    // Trilinear corner weights (corner bit set -> w, else 1-w), CORNERS order
    float ux0 = 1.0f - wx, ux1 = wx;
    float uy0 = 1.0f - wy, uy1 = wy;
    float uz0 = 1.0f - wz, uz1 = wz;

    float w000 = ux0 * uy0 * uz0;
    float w001 = ux0 * uy0 * uz1;
    float w010 = ux0 * uy1 * uz0;
    float w011 = ux0 * uy1 * uz1;
    float w100 = ux1 * uy0 * uz0;
    float w101 = ux1 * uy0 * uz1;
    float w110 = ux1 * uy1 * uz0;
    float w111 = ux1 * uy1 * uz1;

    float2 acc;
    acc.x = w000 * v0[0].x + w001 * v0[1].x + w010 * v0[2].x + w011 * v0[3].x
          + w100 * v1[0].x + w101 * v1[1].x + w110 * v1[2].x + w111 * v1[3].x;
    acc.y = w000 * v0[0].y + w001 * v0[1].y + w010 * v0[2].y + w011 * v0[3].y
          + w100 * v1[0].y + w101 * v1[1].y + w110 * v1[2].y + w111 * v1[3].y;

    // out[n, l] as float2 -> contiguous 256B per warp
    out[(size_t)n * NLEV + l] = acc;
}

extern "C" void kernel_launch(void* const* d_in, const int* in_sizes, int n_in,
                              void* d_out, int out_size)
{
    const float*  pts    = (const float*)d_in[0];   // [N,3] float32
    const float2* tables = (const float2*)d_in[1];  // [L,T,2] float32 -> [L,T] float2

    // Replicate numpy exactly (float64 libm chain)
    ResArr res;
    {
        double growth = exp((log(2048.0) - log(16.0)) / 15.0);
        for (int l = 0; l < NLEV; l++)
            res.r[l] = (float)floor(16.0 * pow(growth, (double)l));
    }

    int total = NPTS * NLEV;           // 8388608, divides 256 exactly
    int block = 256;
    int grid  = total / block;
    ingp_encode_kernel<<<grid, block>>>(pts, tables, (float2*)d_out, res);
}

// round 3
// speedup vs baseline: 1.1085x; 1.0004x over previous
#include <cuda_runtime.h>
#include <math.h>
#include <stdint.h>

// INGP hashgrid encoding, persistent-block version.
//   out[n, l*2+f] = sum_{8 corners} w_c * tables[l, hash(corner) & (T-1), f]
// N = 524288, L = 16, T = 2^19, F = 2.
//
// Levels 0 (res 16 -> 17^3 cells) and 1 (res 22 -> 23^3 cells) are densified
// into a compact 136.6 KB array (kernel A), held in shared memory by a
// persistent kernel -> their 8 gathers become cheap LDS instead of scattered
// LDG wavefronts, and stop touching L2.
// Levels >= 2: hashed LDG with even-ix float4 pairing (x-corners idx/idx^1
// share an aligned float4 when ix is even), .cg (they thrash L1).

#define NPTS   524288
#define NLEV   16
#define TSIZE  (1u << 19)
#define HMASK  (TSIZE - 1u)
#define PRIME1 2654435761u
#define PRIME2 805459861u

// dense level dims: res0=16 -> 17, res1=22 -> 23  (x in [0,1) so ix<=res-1, corner<=res)
#define DIM0   17
#define N0     (DIM0*DIM0*DIM0)          // 4913
#define DIM1   23
#define N1     (DIM1*DIM1*DIM1)          // 12167
#define NDENSE (N0 + N1)                 // 17080
#define SMEM_BYTES (NDENSE * 8)          // 136640

struct ResArr { float r[NLEV]; };

__device__ float2 g_dense[NDENSE];

// ---- Kernel A: densify levels 0,1 : g_dense[cell] = tables[l][hash(cell)] ----
__global__ void ingp_densify_kernel(const float2* __restrict__ tables)
{
    int id = blockIdx.x * blockDim.x + threadIdx.x;
    if (id >= NDENSE) return;
    int l, j, dim;
    if (id < N0) { l = 0; j = id;      dim = DIM0; }
    else         { l = 1; j = id - N0; dim = DIM1; }
    uint32_t iz = (uint32_t)(j % dim);
    uint32_t iy = (uint32_t)((j / dim) % dim);
    uint32_t ix = (uint32_t)(j / (dim * dim));
    uint32_t h = (ix ^ (iy * PRIME1) ^ (iz * PRIME2)) & HMASK;
    g_dense[id] = tables[(size_t)l * TSIZE + h];
}

// ---- Main persistent kernel ----
__global__ __launch_bounds__(1024, 1) void ingp_encode_kernel(
    const float*  __restrict__ pts,     // [N,3]
    const float2* __restrict__ tables,  // [L, T] float2
    float2*       __restrict__ out,     // [N, 16] float2
    ResArr res)
{
    extern __shared__ float2 s_dense[];   // [NDENSE]

    // Coalesced smem fill (once per block; persistent -> amortized over ~55K items)
    {
        const float4* src = (const float4*)g_dense;
        float4*       dst = (float4*)s_dense;
        for (int i = threadIdx.x; i < NDENSE / 2; i += blockDim.x)
            dst[i] = src[i];
    }
    __syncthreads();

    const int total  = NPTS * NLEV;
    const int stride = gridDim.x * blockDim.x;

    for (int t = blockIdx.x * blockDim.x + threadIdx.x; t < total; t += stride) {
        int n = t >> 4;          // point
        int l = t & 15;          // level

        // 16 consecutive threads share a point -> L1 broadcast
        float px = pts[3 * n + 0];
        float py = pts[3 * n + 1];
        float pz = pts[3 * n + 2];

        // x = (p + 1)/2, exact ops (no FMA contraction)
        float xs = __fmul_rn(__fadd_rn(px, 1.0f), 0.5f);
        float ys = __fmul_rn(__fadd_rn(py, 1.0f), 0.5f);
        float zs = __fmul_rn(__fadd_rn(pz, 1.0f), 0.5f);

        float r = res.r[l];
        float posx = __fmul_rn(xs, r);
        float posy = __fmul_rn(ys, r);
        float posz = __fmul_rn(zs, r);

        float fx = floorf(posx), fy = floorf(posy), fz = floorf(posz);
        float wx = __fsub_rn(posx, fx);
        float wy = __fsub_rn(posy, fy);
        float wz = __fsub_rn(posz, fz);

        uint32_t ix = (uint32_t)fx;
        uint32_t iy = (uint32_t)fy;
        uint32_t iz = (uint32_t)fz;

        float2 v0[4];   // x=0 corner per (y,z) pair, CORNERS order (y0z0,y0z1,y1z0,y1z1)
        float2 v1[4];   // x=1 corner per (y,z) pair

        if (l < 2) {
            // ---- dense shared-memory path ----
            int dim  = (l == 0) ? DIM0 : DIM1;
            int base = (l == 0) ? 0 : N0;
            int d2   = dim * dim;
            int c000 = base + (int)ix * d2 + (int)iy * dim + (int)iz;
            v0[0] = s_dense[c000];
            v0[1] = s_dense[c000 + 1];
            v0[2] = s_dense[c000 + dim];
            v0[3] = s_dense[c000 + dim + 1];
            v1[0] = s_dense[c000 + d2];
            v1[1] = s_dense[c000 + d2 + 1];
            v1[2] = s_dense[c000 + d2 + dim];
            v1[3] = s_dense[c000 + d2 + dim + 1];
        } else {
            // ---- hashed global path ----
            uint32_t hy0 = iy * PRIME1;
            uint32_t hy1 = hy0 + PRIME1;
            uint32_t hz0 = iz * PRIME2;
            uint32_t hz1 = hz0 + PRIME2;
            uint32_t rest[4];
            rest[0] = hy0 ^ hz0;
            rest[1] = hy0 ^ hz1;
            rest[2] = hy1 ^ hz0;
            rest[3] = hy1 ^ hz1;

            const float2* __restrict__ tab  = tables + (size_t)l * TSIZE;
            const float4* __restrict__ tab4 = (const float4*)tab;

            if ((ix & 1u) == 0u) {
                // even ix: both x-corners in one aligned float4
                #pragma unroll
                for (int i = 0; i < 4; i++) {
                    uint32_t b = (ix ^ rest[i]) & HMASK;
                    float4 q = __ldcg(tab4 + (b >> 1));
                    bool lo = (b & 1u) == 0u;
                    v0[i] = lo ? make_float2(q.x, q.y) : make_float2(q.z, q.w);
                    v1[i] = lo ? make_float2(q.z, q.w) : make_float2(q.x, q.y);
                }
            } else {
                uint32_t ix1 = ix + 1u;
                #pragma unroll
                for (int i = 0; i < 4; i++) {
                    v0[i] = __ldcg(tab + ((ix  ^ rest[i]) & HMASK));
                    v1[i] = __ldcg(tab + ((ix1 ^ rest[i]) & HMASK));
                }
            }
        }

        // Trilinear weights (corner bit set -> w, else 1-w)
        float ux0 = 1.0f - wx, ux1 = wx;
        float uy0 = 1.0f - wy, uy1 = wy;
        float uz0 = 1.0f - wz, uz1 = wz;

        float w000 = ux0 * uy0 * uz0;
        float w001 = ux0 * uy0 * uz1;
        float w010 = ux0 * uy1 * uz0;
        float w011 = ux0 * uy1 * uz1;
        float w100 = ux1 * uy0 * uz0;
        float w101 = ux1 * uy0 * uz1;
        float w110 = ux1 * uy1 * uz0;
        float w111 = ux1 * uy1 * uz1;

        float2 acc;
        acc.x = w000 * v0[0].x + w001 * v0[1].x + w010 * v0[2].x + w011 * v0[3].x
              + w100 * v1[0].x + w101 * v1[1].x + w110 * v1[2].x + w111 * v1[3].x;
        acc.y = w000 * v0[0].y + w001 * v0[1].y + w010 * v0[2].y + w011 * v0[3].y
              + w100 * v1[0].y + w101 * v1[1].y + w110 * v1[2].y + w111 * v1[3].y;

        out[(size_t)n * NLEV + l] = acc;   // coalesced (16 consecutive float2 / point group)
    }
}

extern "C" void kernel_launch(void* const* d_in, const int* in_sizes, int n_in,
                              void* d_out, int out_size)
{
    const float*  pts    = (const float*)d_in[0];   // [N,3]
    const float2* tables = (const float2*)d_in[1];  // [L,T,2] -> [L,T] float2

    // Replicate numpy RES exactly (float64 libm chain)
    ResArr res;
    {
        double growth = exp((log(2048.0) - log(16.0)) / 15.0);
        for (int l = 0; l < NLEV; l++)
            res.r[l] = (float)floor(16.0 * pow(growth, (double)l));
    }

    // Opt in to >48KB dynamic smem (idempotent, host-side; fine under capture)
    cudaFuncSetAttribute(ingp_encode_kernel,
                         cudaFuncAttributeMaxDynamicSharedMemorySize, SMEM_BYTES);

    int sms = 148;
    cudaDeviceGetAttribute(&sms, cudaDevAttrMultiProcessorCount, 0);

    ingp_densify_kernel<<<(NDENSE + 255) / 256, 256>>>(tables);
    ingp_encode_kernel<<<sms, 1024, SMEM_BYTES>>>(pts, tables, (float2*)d_out, res);
}